// round 1
// baseline (speedup 1.0000x reference)
#include <cuda_runtime.h>

// Masked even-sum reduction over N=2^25 fp32 values.
// HBM-bound: read 128 MiB once, output 1 float.

static constexpr int BLOCK = 256;
static constexpr int GRID  = 148 * 8;   // 8 CTAs/SM on 148 SMs (GB300 has 152; 148 is safe)

__global__ void zero_out_kernel(float* out) {
    out[0] = 0.0f;
}

__global__ __launch_bounds__(BLOCK) void even_sum_kernel(
    const float4* __restrict__ in4, long long n4, float* __restrict__ out)
{
    const long long stride = (long long)gridDim.x * blockDim.x;
    long long i = (long long)blockIdx.x * blockDim.x + threadIdx.x;

    float acc = 0.0f;

    // Grid-stride over float4 elements, unrolled x4 for MLP (16 scalar loads in flight)
    #pragma unroll 4
    for (; i < n4; i += stride) {
        float4 v = in4[i];
        // values are integer-valued floats in [0, 1e6): parity via int conversion is exact
        int a = (int)v.x, b = (int)v.y, c = (int)v.z, d = (int)v.w;
        acc += (a & 1) ? 0.0f : v.x;
        acc += (b & 1) ? 0.0f : v.y;
        acc += (c & 1) ? 0.0f : v.z;
        acc += (d & 1) ? 0.0f : v.w;
    }

    // Warp reduction
    #pragma unroll
    for (int off = 16; off > 0; off >>= 1)
        acc += __shfl_xor_sync(0xFFFFFFFFu, acc, off);

    // Block reduction via shared memory
    __shared__ float warp_sums[BLOCK / 32];
    int lane = threadIdx.x & 31;
    int wid  = threadIdx.x >> 5;
    if (lane == 0) warp_sums[wid] = acc;
    __syncthreads();

    if (wid == 0) {
        float s = (lane < BLOCK / 32) ? warp_sums[lane] : 0.0f;
        #pragma unroll
        for (int off = 4; off > 0; off >>= 1)
            s += __shfl_xor_sync(0xFFFFFFFFu, s, off);
        if (lane == 0)
            atomicAdd(out, s);
    }
}

extern "C" void kernel_launch(void* const* d_in, const int* in_sizes, int n_in,
                              void* d_out, int out_size) {
    const float* items = (const float*)d_in[0];
    float* out = (float*)d_out;
    long long n = in_sizes[0];
    long long n4 = n >> 2;  // N = 2^25, divisible by 4

    zero_out_kernel<<<1, 1>>>(out);
    even_sum_kernel<<<GRID, BLOCK>>>((const float4*)items, n4, out);
}

// round 2
// speedup vs baseline: 1.0531x; 1.0531x over previous
#include <cuda_runtime.h>

// Masked even-sum reduction over N=2^25 fp32 (128 MiB), HBM-bound.
// Single wave: 1024 CTAs x 256 threads, exactly 32 float4 per thread.
// Single kernel: device-global accumulator + arrival counter; last CTA
// publishes the result and resets state for the next graph replay.

static constexpr int BLOCK = 256;
static constexpr int GRID  = 1024;                 // single wave on 148+ SMs at occ>=8
static constexpr int THREADS_TOTAL = GRID * BLOCK; // 262144
static constexpr int ITERS = 32;                   // 2^23 float4 / 262144

__device__ float    g_acc;     // zero at module load; reset by last CTA each run
__device__ unsigned g_count;

__global__ __launch_bounds__(BLOCK) void even_sum_kernel(
    const float4* __restrict__ in4, float* __restrict__ out)
{
    const float4* p = in4 + (blockIdx.x * BLOCK + threadIdx.x);

    float acc = 0.0f;

    #pragma unroll 8
    for (int it = 0; it < ITERS; ++it) {
        float4 v = __ldcs(p + (size_t)it * THREADS_TOTAL);
        // integer-valued floats < 2^24: parity via int conversion is exact
        int a = (int)v.x, b = (int)v.y, c = (int)v.z, d = (int)v.w;
        acc += (a & 1) ? 0.0f : v.x;
        acc += (b & 1) ? 0.0f : v.y;
        acc += (c & 1) ? 0.0f : v.z;
        acc += (d & 1) ? 0.0f : v.w;
    }

    // Warp reduction
    #pragma unroll
    for (int off = 16; off > 0; off >>= 1)
        acc += __shfl_xor_sync(0xFFFFFFFFu, acc, off);

    // Block reduction
    __shared__ float warp_sums[BLOCK / 32];
    int lane = threadIdx.x & 31;
    int wid  = threadIdx.x >> 5;
    if (lane == 0) warp_sums[wid] = acc;
    __syncthreads();

    if (wid == 0) {
        float s = (lane < BLOCK / 32) ? warp_sums[lane] : 0.0f;
        #pragma unroll
        for (int off = 4; off > 0; off >>= 1)
            s += __shfl_xor_sync(0xFFFFFFFFu, s, off);

        if (lane == 0) {
            atomicAdd(&g_acc, s);
            __threadfence();
            unsigned prev = atomicAdd(&g_count, 1u);
            if (prev == GRID - 1) {
                // last CTA: publish result, reset state for next replay
                out[0] = atomicExch(&g_acc, 0.0f);
                g_count = 0;
            }
        }
    }
}

extern "C" void kernel_launch(void* const* d_in, const int* in_sizes, int n_in,
                              void* d_out, int out_size) {
    const float* items = (const float*)d_in[0];
    float* out = (float*)d_out;
    even_sum_kernel<<<GRID, BLOCK>>>((const float4*)items, out);
}